// round 8
// baseline (speedup 1.0000x reference)
#include <cuda_runtime.h>

// FeaturesLinear: out[b,:] = sum_{t<50} user_W[fid[b*50+t]] * rating_W[ridx[b*50+t]]
//                            + item_W[item_ids[b]] + bias
//
// Strategy (R8): rank-sort the 50 history items of each row by rating index
// inside the warp (ballot/popc prefix ranks, zero memory traffic), stage
// packed (fid | flush | ridx) into smem at sorted positions, then run a
// COMPILE-TIME 50-iteration flat loop:
//    s += user_W[fid]                      (independent LDG.128 -> high MLP)
//    if (flush) acc = fma(s, rating_W[r], acc); s = 0;   (<=10 uniform flushes)
// This keeps R7's wavefront savings (<=10 rating LDS.128 per row instead of 50,
// no broadcast id LDGs) while restoring R5's memory-level parallelism.
//
// Inputs (metadata order):
//   d_in[0] feature_ids int32 [819200]
//   d_in[1] ratings     f32   [819200]
//   d_in[2] segment_ids int32 [819200]  (contiguous repeat(arange(B),50) -> implicit)
//   d_in[3] item_ids    int32 [16384]
//   d_in[4] user_W      f32   [100001,128]
//   d_in[5] rating_W    f32   [10,128]
//   d_in[6] item_W      f32   [100000,128]
//   d_in[7] bias        f32   [128]
// Output: f32 [16384,128]

#define BATCH  16384
#define HIST   50
#define WARPS_PER_CTA 8
#define THREADS (WARPS_PER_CTA * 32)

__global__ void __launch_bounds__(THREADS)
features_linear_kernel(const int*    __restrict__ feature_ids,
                       const float*  __restrict__ ratings,
                       const int*    __restrict__ item_ids,
                       const float4* __restrict__ user_W,    // [100001, 32] float4
                       const float4* __restrict__ rating_W,  // [10, 32]     float4
                       const float4* __restrict__ item_W,    // [100000, 32] float4
                       const float4* __restrict__ bias,      // [32]         float4
                       float4*       __restrict__ out)       // [16384, 32]  float4
{
    __shared__ float4 s_rw[10 * 32];                 // 5 KB rating table
    __shared__ int    s_ids[WARPS_PER_CTA * HIST];   // sorted packed ids per warp

    const int tid = threadIdx.x;
    for (int i = tid; i < 10 * 32; i += THREADS)
        s_rw[i] = rating_W[i];
    __syncthreads();

    const int warp = tid >> 5;
    const int lane = tid & 31;
    const int row  = blockIdx.x * WARPS_PER_CTA + warp;   // one warp per row
    const int base = row * HIST;
    const int wbase = warp * HIST;
    const unsigned FULL = 0xffffffffu;

    // ---- Stage ids coalesced: item A = t=lane, item B = t=32+lane ---------
    const bool vB = (lane < (HIST - 32));
    const int   fidA = __ldg(&feature_ids[base + lane]);
    const float ratA = __ldg(&ratings[base + lane]);
    int   fidB = 0;
    float ratB = 0.f;
    if (vB) {
        fidB = __ldg(&feature_ids[base + 32 + lane]);
        ratB = __ldg(&ratings[base + 32 + lane]);
    }
    const int ra = __float2int_rn((ratA - 0.5f) * 2.0f);          // 0..9
    const int rb = vB ? __float2int_rn((ratB - 0.5f) * 2.0f) : 15; // sentinel

    // ---- Warp rank-sort by rating: ballot prefix ranks (ALU only) ---------
    const unsigned lt = (1u << lane) - 1u;
    int pos = 0;
    int rankA = 0, rankB = 0;
    int flA = 0, flB = 0;        // "last item of its bucket" flags
    #pragma unroll
    for (int r = 0; r < 10; ++r) {
        const unsigned bA = __ballot_sync(FULL, ra == r);
        const unsigned bB = __ballot_sync(FULL, rb == r);
        const int cA = __popc(bA), cB = __popc(bB);
        if (ra == r) {
            rankA = pos + __popc(bA & lt);
            flA   = (rankA == pos + cA + cB - 1);
        }
        if (rb == r) {
            rankB = pos + cA + __popc(bB & lt);
            flB   = (rankB == pos + cA + cB - 1);
        }
        pos += cA + cB;
    }

    // packed: fid(17b) << 5 | flush << 4 | ridx(4b)
    s_ids[wbase + rankA] = (fidA << 5) | (flA << 4) | ra;
    if (vB)
        s_ids[wbase + rankB] = (fidB << 5) | (flB << 4) | rb;
    __syncwarp();

    // ---- Flat compile-time loop over sorted items --------------------------
    float4 acc = make_float4(0.f, 0.f, 0.f, 0.f);
    float4 s   = make_float4(0.f, 0.f, 0.f, 0.f);

    #pragma unroll
    for (int k = 0; k < HIST; ++k) {
        const int p = s_ids[wbase + k];                    // broadcast LDS
        const float4 u = __ldg(&user_W[(p >> 5) * 32 + lane]);  // gather
        s.x += u.x; s.y += u.y; s.z += u.z; s.w += u.w;
        if (p & 16) {                                      // uniform, <=10 taken
            const float4 rv = s_rw[(p & 15) * 32 + lane];
            acc.x = fmaf(s.x, rv.x, acc.x);
            acc.y = fmaf(s.y, rv.y, acc.y);
            acc.z = fmaf(s.z, rv.z, acc.z);
            acc.w = fmaf(s.w, rv.w, acc.w);
            s = make_float4(0.f, 0.f, 0.f, 0.f);
        }
    }

    // ---- Epilogue: item embedding + bias -----------------------------------
    const int iid = __ldg(&item_ids[row]);
    const float4 iv = __ldg(&item_W[iid * 32 + lane]);
    const float4 bv = __ldg(&bias[lane]);

    acc.x += iv.x + bv.x;
    acc.y += iv.y + bv.y;
    acc.z += iv.z + bv.z;
    acc.w += iv.w + bv.w;

    out[row * 32 + lane] = acc;
}

extern "C" void kernel_launch(void* const* d_in, const int* in_sizes, int n_in,
                              void* d_out, int out_size)
{
    const int*    feature_ids = (const int*)  d_in[0];
    const float*  ratings     = (const float*)d_in[1];
    // d_in[2] segment_ids: repeat(arange(BATCH), HIST) -> implicit in layout
    const int*    item_ids = (const int*)   d_in[3];
    const float4* user_W   = (const float4*)d_in[4];
    const float4* rating_W = (const float4*)d_in[5];
    const float4* item_W   = (const float4*)d_in[6];
    const float4* bias     = (const float4*)d_in[7];
    float4*       out      = (float4*)      d_out;

    const int grid = BATCH / WARPS_PER_CTA;   // 2048 CTAs, 8 warps each
    features_linear_kernel<<<grid, THREADS>>>(
        feature_ids, ratings, item_ids, user_W, rating_W, item_W, bias, out);
}

// round 11
// speedup vs baseline: 1.0718x; 1.0718x over previous
#include <cuda_runtime.h>

// FeaturesLinear: out[b,:] = sum_{t<50} user_W[fid[b*50+t]] * rating_W[ridx[b*50+t]]
//                            + item_W[item_ids[b]] + bias
//
// R9 strategy: per-warp ballot rank-sort of the 50 history items by rating
// index (ALU only), recording (offset,count) per bucket. Main loop = 10 static
// bucket blocks, each a branch-light inner loop unrolled x4 with FOUR
// independent accumulator chains (MLP=4 on the user_W gathers), summing RAW
// user vectors. rating_W is applied once per non-empty bucket (<=10 LDS.128
// per row instead of 50). No per-item branch, no flag unpacking (R8's
// issue-bound failure mode), no dynamic single-chain walk (R7's latency-bound
// failure mode).
//
// Inputs (metadata order):
//   d_in[0] feature_ids int32 [819200]
//   d_in[1] ratings     f32   [819200]
//   d_in[2] segment_ids int32 [819200]  (contiguous repeat(arange(B),50) -> implicit)
//   d_in[3] item_ids    int32 [16384]
//   d_in[4] user_W      f32   [100001,128]
//   d_in[5] rating_W    f32   [10,128]
//   d_in[6] item_W      f32   [100000,128]
//   d_in[7] bias        f32   [128]
// Output: f32 [16384,128]

#define BATCH  16384
#define HIST   50
#define WARPS_PER_CTA 8
#define THREADS (WARPS_PER_CTA * 32)

__global__ void __launch_bounds__(THREADS)
features_linear_kernel(const int*    __restrict__ feature_ids,
                       const float*  __restrict__ ratings,
                       const int*    __restrict__ item_ids,
                       const float4* __restrict__ user_W,    // [100001, 32] float4
                       const float4* __restrict__ rating_W,  // [10, 32]     float4
                       const float4* __restrict__ item_W,    // [100000, 32] float4
                       const float4* __restrict__ bias,      // [32]         float4
                       float4*       __restrict__ out)       // [16384, 32]  float4
{
    __shared__ float4 s_rw[10 * 32];                 // 5 KB rating table
    __shared__ int    s_ids[WARPS_PER_CTA * HIST];   // sorted fids per warp
    __shared__ int    s_cnt[WARPS_PER_CTA * 10];     // (offset<<8)|count per bucket

    const int tid = threadIdx.x;
    for (int i = tid; i < 10 * 32; i += THREADS)
        s_rw[i] = rating_W[i];
    __syncthreads();

    const int warp  = tid >> 5;
    const int lane  = tid & 31;
    const int row   = blockIdx.x * WARPS_PER_CTA + warp;   // one warp per row
    const int base  = row * HIST;
    const int wbase = warp * HIST;
    const int w10   = warp * 10;
    const unsigned FULL = 0xffffffffu;

    // ---- Epilogue prefetch (overlaps with sort + main loop) ----------------
    const int    iid = __ldg(&item_ids[row]);
    const float4 iv  = __ldg(&item_W[iid * 32 + lane]);
    const float4 bv  = __ldg(&bias[lane]);

    // ---- Stage ids coalesced: item A = t=lane, item B = t=32+lane ----------
    const bool vB = (lane < (HIST - 32));
    const int   fidA = __ldg(&feature_ids[base + lane]);
    const float ratA = __ldg(&ratings[base + lane]);
    int   fidB = 0;
    float ratB = 0.f;
    if (vB) {
        fidB = __ldg(&feature_ids[base + 32 + lane]);
        ratB = __ldg(&ratings[base + 32 + lane]);
    }
    const int ra = __float2int_rn((ratA - 0.5f) * 2.0f);           // 0..9
    const int rb = vB ? __float2int_rn((ratB - 0.5f) * 2.0f) : 15; // sentinel

    // ---- Warp rank-sort by rating: ballot prefix ranks (ALU only) ----------
    const unsigned lt = (1u << lane) - 1u;
    int pos = 0, rankA = 0, rankB = 0;
    #pragma unroll
    for (int r = 0; r < 10; ++r) {
        const unsigned bA = __ballot_sync(FULL, ra == r);
        const unsigned bB = __ballot_sync(FULL, rb == r);
        const int cA = __popc(bA), cB = __popc(bB);
        if (ra == r) rankA = pos + __popc(bA & lt);
        if (rb == r) rankB = pos + cA + __popc(bB & lt);
        if (lane == r) s_cnt[w10 + r] = (pos << 8) | (cA + cB);
        pos += cA + cB;
    }
    s_ids[wbase + rankA] = fidA;
    if (vB) s_ids[wbase + rankB] = fidB;
    __syncwarp();

    // ---- Main loop: 10 static bucket blocks, inner unrolled x4, MLP=4 ------
    float4 acc = make_float4(0.f, 0.f, 0.f, 0.f);

    #pragma unroll
    for (int r = 0; r < 10; ++r) {
        const int oc = s_cnt[w10 + r];                 // broadcast LDS
        const int c  = oc & 255;
        if (c == 0) continue;                          // warp-uniform skip
        const int o  = wbase + (oc >> 8);

        float4 s0 = make_float4(0.f, 0.f, 0.f, 0.f);
        float4 s1 = s0, s2 = s0, s3 = s0;

        for (int j = 0; j < c; j += 4) {
            // Four independent gather->accumulate chains.
            const int f0 = s_ids[o + j];
            const float4 u0 = __ldg(&user_W[f0 * 32 + lane]);
            if (j + 1 < c) {
                const int f1 = s_ids[o + j + 1];
                const float4 u1 = __ldg(&user_W[f1 * 32 + lane]);
                s1.x += u1.x; s1.y += u1.y; s1.z += u1.z; s1.w += u1.w;
            }
            if (j + 2 < c) {
                const int f2 = s_ids[o + j + 2];
                const float4 u2 = __ldg(&user_W[f2 * 32 + lane]);
                s2.x += u2.x; s2.y += u2.y; s2.z += u2.z; s2.w += u2.w;
            }
            if (j + 3 < c) {
                const int f3 = s_ids[o + j + 3];
                const float4 u3 = __ldg(&user_W[f3 * 32 + lane]);
                s3.x += u3.x; s3.y += u3.y; s3.z += u3.z; s3.w += u3.w;
            }
            s0.x += u0.x; s0.y += u0.y; s0.z += u0.z; s0.w += u0.w;
        }

        // One rating vector per bucket.
        const float4 rv = s_rw[r * 32 + lane];
        acc.x = fmaf((s0.x + s1.x) + (s2.x + s3.x), rv.x, acc.x);
        acc.y = fmaf((s0.y + s1.y) + (s2.y + s3.y), rv.y, acc.y);
        acc.z = fmaf((s0.z + s1.z) + (s2.z + s3.z), rv.z, acc.z);
        acc.w = fmaf((s0.w + s1.w) + (s2.w + s3.w), rv.w, acc.w);
    }

    // ---- Epilogue: item embedding + bias -----------------------------------
    acc.x += iv.x + bv.x;
    acc.y += iv.y + bv.y;
    acc.z += iv.z + bv.z;
    acc.w += iv.w + bv.w;

    out[row * 32 + lane] = acc;
}

extern "C" void kernel_launch(void* const* d_in, const int* in_sizes, int n_in,
                              void* d_out, int out_size)
{
    const int*    feature_ids = (const int*)  d_in[0];
    const float*  ratings     = (const float*)d_in[1];
    // d_in[2] segment_ids: repeat(arange(BATCH), HIST) -> implicit in layout
    const int*    item_ids = (const int*)   d_in[3];
    const float4* user_W   = (const float4*)d_in[4];
    const float4* rating_W = (const float4*)d_in[5];
    const float4* item_W   = (const float4*)d_in[6];
    const float4* bias     = (const float4*)d_in[7];
    float4*       out      = (float4*)      d_out;

    const int grid = BATCH / WARPS_PER_CTA;   // 2048 CTAs, 8 warps each
    features_linear_kernel<<<grid, THREADS>>>(
        feature_ids, ratings, item_ids, user_W, rating_W, item_W, bias, out);
}